// round 12
// baseline (speedup 1.0000x reference)
#include <cuda_runtime.h>
#include <cuda_bf16.h>
#include <math.h>

#define NN 20000
#define EE 640000
#define HH 128
#define NB 16

// ---------------- scratch ----------------
__device__ int   g_src[EE];
__device__ int   g_dst[EE];
__device__ float g_e[(size_t)NN * 128];
__device__ float g_p[(size_t)NN * 128];      // P = e @ (Wq Wk^T)
__device__ float g_sv[NN];                   // e_n · (Wk bq)
__device__ float g_ev[(size_t)NN * 3];
__device__ int g_counts[NN];                 // 0 at prep entry; scan resets
__device__ int g_offs[NN + 1];
__device__ int g_cursor[NN];
__device__ unsigned g_pk[EE];                // src | (bin<<20), CSR-ordered by dst
__device__ unsigned short g_pdst[EE];        // dst per CSR position
__device__ float g_ex[EE];                   // exp(adjusted logit) per CSR position
__device__ __align__(16) float g_v[128];     // Wk bq
__device__ float g_zero[128];                // stays 0 (static zero-init, never written)

// packed bf16 hi/lo pair tables
__device__ uint2 g_xpk[(size_t)NN * 64];
__device__ uint2 g_tpk[(size_t)NN * 64];
__device__ uint2 g_epk[(size_t)NN * 64];
__device__ uint2 g_w1t[128 * 128];
__device__ uint2 g_w2t[128 * 64];
__device__ uint2 g_wat[128 * 64];            // packed A = Wq Wk^T

// ---------------- helpers ----------------
__device__ __forceinline__ void split2(float f0, float f1, unsigned& hi, unsigned& lo) {
    __nv_bfloat162 h = __floats2bfloat162_rn(f0, f1);
    float r0 = f0 - __bfloat162float(h.x);
    float r1 = f1 - __bfloat162float(h.y);
    __nv_bfloat162 l = __floats2bfloat162_rn(r0, r1);
    hi = *reinterpret_cast<unsigned*>(&h);
    lo = *reinterpret_cast<unsigned*>(&l);
}
__device__ __forceinline__ void mma16(float* c, unsigned a0, unsigned a1, unsigned a2, unsigned a3,
                                      unsigned b0, unsigned b1) {
    asm volatile(
        "mma.sync.aligned.m16n8k16.row.col.f32.bf16.bf16.f32 "
        "{%0,%1,%2,%3},{%4,%5,%6,%7},{%8,%9},{%0,%1,%2,%3};"
        : "+f"(c[0]), "+f"(c[1]), "+f"(c[2]), "+f"(c[3])
        : "r"(a0), "r"(a1), "r"(a2), "r"(a3), "r"(b0), "r"(b1));
}

// ---------------- packers ----------------
__global__ void pack_x_kernel(const float* __restrict__ x) {
    int idx = blockIdx.x * blockDim.x + threadIdx.x;
    if (idx >= NN * 64) return;
    float2 v = ((const float2*)x)[idx];
    unsigned h, l;
    split2(v.x, v.y, h, l);
    g_xpk[idx] = make_uint2(h, l);
}

__global__ void pack_w_kernel(const float* __restrict__ W1, const float* __restrict__ W2) {
    int y = blockIdx.y;
    const float* W = (y == 0) ? W1 : W2;
    uint2* Wt = (y == 0) ? g_w1t : g_w2t;
    int jmax = (y == 0) ? 128 : 64;
    int idx = blockIdx.x * blockDim.x + threadIdx.x;
    if (idx >= 128 * jmax) return;
    int col = idx / jmax, j = idx % jmax;
    float w0 = W[(size_t)(2 * j) * 128 + col];
    float w1 = W[(size_t)(2 * j + 1) * 128 + col];
    unsigned h, l;
    split2(w0, w1, h, l);
    Wt[col * jmax + j] = make_uint2(h, l);
}

// A[a][b] = sum_o Wq[a][o]*Wk[b][o]; packed pairs along a. Also v = Wk·bq.
__global__ void attn_prep_kernel(const float* __restrict__ Wq, const float* __restrict__ Wk,
                                 const float* __restrict__ bq) {
    int idx = blockIdx.x * blockDim.x + threadIdx.x;
    if (idx >= 128 * 64) return;
    int b = idx >> 6;       // out col 0..127
    int j = idx & 63;       // a-pair 0..63
    const float* wq0 = Wq + (size_t)(2 * j) * 128;
    const float* wq1 = Wq + (size_t)(2 * j + 1) * 128;
    const float* wkb = Wk + (size_t)b * 128;
    float a0 = 0.f, a1 = 0.f;
    #pragma unroll 8
    for (int o = 0; o < 128; o++) {
        float w = wkb[o];
        a0 += wq0[o] * w;
        a1 += wq1[o] * w;
    }
    unsigned h, l;
    split2(a0, a1, h, l);
    g_wat[b * 64 + j] = make_uint2(h, l);
    if (idx < 128) {
        const float* wk = Wk + (size_t)idx * 128;
        float s = 0.f;
        #pragma unroll 8
        for (int o = 0; o < 128; o++) s += wk[o] * bq[o];
        g_v[idx] = s;
    }
}

// ---------------- prep: dtype-detect + normalize + histogram + ev (i<NN) ----------------
__global__ void prep_kernel(const int* __restrict__ ei_raw, const float* __restrict__ pos) {
    __shared__ int s_is64;
    if (threadIdx.x == 0) {
        int allzero = 1;
        #pragma unroll
        for (int i = 1; i < 128; i += 2)
            if (ei_raw[i] != 0) allzero = 0;
        s_is64 = allzero;
    }
    __syncthreads();
    int i = blockIdx.x * blockDim.x + threadIdx.x;
    if (i >= EE) return;
    int s, d;
    if (s_is64) {
        const long long* e = (const long long*)ei_raw;
        s = (int)e[i];
        d = (int)e[(size_t)EE + i];
    } else {
        s = ei_raw[i];
        d = ei_raw[EE + i];
    }
    g_src[i] = s;
    g_dst[i] = d;
    atomicAdd(&g_counts[d], 1);
    if (i < NN) {
        float vx = pos[d * 3 + 0] - pos[s * 3 + 0];
        float vy = pos[d * 3 + 1] - pos[s * 3 + 1];
        float vz = pos[d * 3 + 2] - pos[s * 3 + 2];
        float inv = 1.0f / (sqrtf(vx * vx + vy * vy + vz * vz) + 1e-8f);
        g_ev[i * 3 + 0] = vx * inv;
        g_ev[i * 3 + 1] = vy * inv;
        g_ev[i * 3 + 2] = vz * inv;
    }
}

// ---------------- scan (also resets counts) ----------------
__global__ void scan_offsets_kernel() {
    __shared__ int sh_carry;
    __shared__ int wsum[32];
    int tid = threadIdx.x, lane = tid & 31, wid = tid >> 5;
    if (tid == 0) sh_carry = 0;
    __syncthreads();
    for (int base = 0; base < NN; base += 1024) {
        int c0 = sh_carry;
        int i = base + tid;
        int v = (i < NN) ? g_counts[i] : 0;
        if (i < NN) g_counts[i] = 0;
        int x = v;
        #pragma unroll
        for (int off = 1; off < 32; off <<= 1) {
            int y = __shfl_up_sync(~0u, x, off);
            if (lane >= off) x += y;
        }
        if (lane == 31) wsum[wid] = x;
        __syncthreads();
        if (wid == 0) {
            int ws = wsum[lane];
            #pragma unroll
            for (int off = 1; off < 32; off <<= 1) {
                int y = __shfl_up_sync(~0u, ws, off);
                if (lane >= off) ws += y;
            }
            wsum[lane] = ws;
        }
        __syncthreads();
        int incl = c0 + x + (wid ? wsum[wid - 1] : 0);
        if (i < NN) { g_offs[i] = incl - v; g_cursor[i] = incl - v; }
        __syncthreads();
        if (tid == 1023) sh_carry = incl;
        __syncthreads();
    }
    if (threadIdx.x == 0) g_offs[NN] = sh_carry;
}

// ---------------- scatter: CSR order, pack src + angle bin, store dst ----------------
__global__ void scatter_edges_kernel() {
    int i = blockIdx.x * blockDim.x + threadIdx.x;
    if (i >= EE) return;
    int s = g_src[i];
    int d = g_dst[i];
    float c = g_ev[d * 3 + 0] * g_ev[s * 3 + 0]
            + g_ev[d * 3 + 1] * g_ev[s * 3 + 1]
            + g_ev[d * 3 + 2] * g_ev[s * 3 + 2];
    c = fminf(fmaxf(c, -1.f), 1.f);
    int cnt = 0;
    #pragma unroll
    for (int t = 0; t < 17; t++) cnt += ((-1.f + 0.125f * (float)t) < c) ? 1 : 0;
    int b = min(max(cnt - 1, 0), NB - 1);
    int p = atomicAdd(&g_cursor[d], 1);
    g_pk[p] = (unsigned)s | ((unsigned)b << 20);
    g_pdst[p] = (unsigned short)d;
}

// ================= packed bf16 GEMM (unchanged) =================
template<int K, int GATHER, int ACT, int WPK, int WF32>
__device__ __forceinline__ void gemm_pk_body(
    const uint2* __restrict__ Apk, const uint2* __restrict__ Wt,
    const float* __restrict__ bias, float* __restrict__ C,
    uint2* __restrict__ Cpk, int M)
{
    __shared__ __align__(16) uint2 Bs[2][128][20];
    int tid = threadIdx.x, lane = tid & 31, wid = tid >> 5;
    int gid = lane >> 2, tig = lane & 3;
    int warpRow = (wid & 3) * 32;
    int warpCol = (wid >> 2) * 64;
    int rowBase = blockIdx.x * 128;
    const int NT = K / 32;
    const int AJ = GATHER ? 64 : (K / 2);

    const uint2* ap[4];
    const uint2* ap2[4];
    #pragma unroll
    for (int i = 0; i < 4; i++) {
        int gr = rowBase + warpRow + i * 8 + gid;
        int row = (gr < M) ? gr : 0;
        if (GATHER) {
            ap[i]  = Apk + (size_t)g_src[row] * 64;
            ap2[i] = Apk + (size_t)g_dst[row] * 64;
        } else {
            ap[i] = Apk + (size_t)row * AJ;
        }
    }

    float acc[2][8][4];
    #pragma unroll
    for (int m = 0; m < 2; m++)
        #pragma unroll
        for (int n = 0; n < 8; n++)
            #pragma unroll
            for (int j = 0; j < 4; j++) acc[m][n][j] = 0.f;

    #pragma unroll
    for (int rr = 0; rr < 8; rr++) {
        int idx = tid + rr * 256;
        int col = idx >> 4, j = idx & 15;
        Bs[0][col][j] = Wt[(size_t)col * (K / 2) + j];
    }
    __syncthreads();

    #pragma unroll
    for (int t = 0; t < NT; t++) {
        if (t + 1 < NT) {
            #pragma unroll
            for (int rr = 0; rr < 8; rr++) {
                int idx = tid + rr * 256;
                int col = idx >> 4, j = idx & 15;
                Bs[(t + 1) & 1][col][j] = Wt[(size_t)col * (K / 2) + (t + 1) * 16 + j];
            }
        }
        const uint2* ab[4];
        int jt;
        if (GATHER) {
            bool first = t < NT / 2;
            #pragma unroll
            for (int i = 0; i < 4; i++) ab[i] = first ? ap[i] : ap2[i];
            jt = (first ? t : t - NT / 2) * 16;
        } else {
            #pragma unroll
            for (int i = 0; i < 4; i++) ab[i] = ap[i];
            jt = t * 16;
        }

        #pragma unroll
        for (int s = 0; s < 2; s++) {
            int ja = jt + s * 8;
            uint2 A0[4], A1[4];
            #pragma unroll
            for (int i = 0; i < 4; i++) {
                A0[i] = ab[i][ja + tig];
                A1[i] = ab[i][ja + tig + 4];
            }
            #pragma unroll
            for (int n = 0; n < 8; n++) {
                int col = warpCol + n * 8 + gid;
                uint2 b0 = Bs[t & 1][col][s * 8 + tig];
                uint2 b1 = Bs[t & 1][col][s * 8 + tig + 4];
                #pragma unroll
                for (int m = 0; m < 2; m++) {
                    mma16(acc[m][n], A0[2*m].x, A0[2*m+1].x, A1[2*m].x, A1[2*m+1].x, b0.x, b1.x);
                    mma16(acc[m][n], A0[2*m].x, A0[2*m+1].x, A1[2*m].x, A1[2*m+1].x, b0.y, b1.y);
                    mma16(acc[m][n], A0[2*m].y, A0[2*m+1].y, A1[2*m].y, A1[2*m+1].y, b0.x, b1.x);
                }
            }
        }
        __syncthreads();
    }

    #pragma unroll
    for (int m = 0; m < 2; m++) {
        int r0 = rowBase + warpRow + m * 16 + gid;
        int r1 = r0 + 8;
        #pragma unroll
        for (int n = 0; n < 8; n++) {
            int col = warpCol + n * 8 + tig * 2;
            float bz0 = bias[col], bz1 = bias[col + 1];
            float v0 = acc[m][n][0] + bz0, v1 = acc[m][n][1] + bz1;
            float v2 = acc[m][n][2] + bz0, v3 = acc[m][n][3] + bz1;
            if (ACT) {
                v0 = v0 / (1.f + expf(-v0)); v1 = v1 / (1.f + expf(-v1));
                v2 = v2 / (1.f + expf(-v2)); v3 = v3 / (1.f + expf(-v3));
            }
            int jout = (warpCol >> 1) + n * 4 + tig;
            if (r0 < M) {
                if (WF32) *(float2*)(C + (size_t)r0 * 128 + col) = make_float2(v0, v1);
                if (WPK) { unsigned h, l; split2(v0, v1, h, l); Cpk[(size_t)r0 * 64 + jout] = make_uint2(h, l); }
            }
            if (r1 < M) {
                if (WF32) *(float2*)(C + (size_t)r1 * 128 + col) = make_float2(v2, v3);
                if (WPK) { unsigned h, l; split2(v2, v3, h, l); Cpk[(size_t)r1 * 64 + jout] = make_uint2(h, l); }
            }
        }
    }
}

__global__ __launch_bounds__(256, 2) void gemm1_kernel(
    const float* __restrict__ b1, int M) {
    gemm_pk_body<256, 1, 1, 1, 0>(g_xpk, g_w1t, b1, nullptr, g_tpk, M);
}
__global__ __launch_bounds__(256, 2) void gemm2_kernel(
    const float* __restrict__ b2, float* __restrict__ e, int M) {
    gemm_pk_body<128, 0, 0, 1, 1>(g_tpk, g_w2t, b2, e, g_epk, M);
}
__global__ __launch_bounds__(256, 2) void gemmP_kernel(int M) {
    gemm_pk_body<128, 0, 0, 0, 1>(g_epk, g_wat, g_zero, g_p, nullptr, M);
}

// ---------------- sv[n] = e_n · v (8 lanes per node) ----------------
__global__ void sv_kernel() {
    int idx = blockIdx.x * blockDim.x + threadIdx.x;
    int node = idx >> 3, sl = idx & 7;
    if (node >= NN) return;
    const float4* er = (const float4*)g_e + (size_t)node * 32;
    const float4* vr = (const float4*)g_v;
    float acc = 0.f;
    #pragma unroll
    for (int i = 0; i < 4; i++) {
        float4 a = er[sl + 8 * i];
        float4 b = vr[sl + 8 * i];
        acc += a.x * b.x + a.y * b.y + a.z * b.z + a.w * b.w;
    }
    #pragma unroll
    for (int off = 4; off; off >>= 1) acc += __shfl_xor_sync(~0u, acc, off, 8);
    if (sl == 0) g_sv[node] = acc;
}

// ---------------- pass 1: edge-parallel logits (quarter-warp per CSR position) ----------
// logit = P_d · e_s + sv_s  (per-d terms cancel in the grouped softmax)
__global__ __launch_bounds__(256) void logit_kernel() {
    int gw = (blockIdx.x * blockDim.x + threadIdx.x) >> 5;   // global warp
    int lane = threadIdx.x & 31;
    int sub = lane >> 3, sl = lane & 7;
    int pos = gw * 4 + sub;
    if (pos >= EE) return;

    unsigned pk = g_pk[pos];
    int s = pk & 0xFFFFF;
    int d = g_pdst[pos];

    const float4* er = (const float4*)g_e + (size_t)s * 32;
    const float4* pr = (const float4*)g_p + (size_t)d * 32;

    float acc = 0.f;
    #pragma unroll
    for (int i = 0; i < 4; i++) {
        float4 a = pr[sl + 8 * i];
        float4 b = er[sl + 8 * i];
        acc += a.x * b.x + a.y * b.y + a.z * b.z + a.w * b.w;
    }
    #pragma unroll
    for (int off = 4; off; off >>= 1) acc += __shfl_xor_sync(~0u, acc, off, 8);
    if (sl == 0) g_ex[pos] = expf((acc + g_sv[s]) * 0.08838834764831843f);   // 1/sqrt(128)
}

// ---------------- pass 2: warp-per-node accumulate (no dot/exp) ----------------
#define ACC_CASE(B) case B: a##B.x += ex*ev.x; a##B.y += ex*ev.y; \
                            a##B.z += ex*ev.z; a##B.w += ex*ev.w; sb##B += ex; break;

__global__ __launch_bounds__(256, 2) void accum_kernel(float* __restrict__ out)
{
    int gw = (blockIdx.x * blockDim.x + threadIdx.x) >> 5;
    int lane = threadIdx.x & 31;
    if (gw >= NN) return;
    int n = gw;

    const float4* e4 = (const float4*)g_e;

    float4 z = make_float4(0.f, 0.f, 0.f, 0.f);
    float4 a0=z,a1=z,a2=z,a3=z,a4=z,a5=z,a6=z,a7=z,
           a8=z,a9=z,a10=z,a11=z,a12=z,a13=z,a14=z,a15=z;
    float sb0=0,sb1=0,sb2=0,sb3=0,sb4=0,sb5=0,sb6=0,sb7=0,
          sb8=0,sb9=0,sb10=0,sb11=0,sb12=0,sb13=0,sb14=0,sb15=0;

    int pos = g_offs[n];
    int end = g_offs[n + 1];

    if (pos < end) {
        unsigned pk = g_pk[pos];
        float ex = g_ex[pos];
        float4 ev = e4[(size_t)(pk & 0xFFFFF) * 32 + lane];
        int b = pk >> 20;

        for (; pos < end; pos++) {
            float4 nev = ev;
            float nex = ex;
            int nb = b;
            if (pos + 1 < end) {
                unsigned npk = g_pk[pos + 1];
                nex = g_ex[pos + 1];
                nev = e4[(size_t)(npk & 0xFFFFF) * 32 + lane];
                nb = npk >> 20;
            }
            switch (b) {
                ACC_CASE(0)  ACC_CASE(1)  ACC_CASE(2)  ACC_CASE(3)
                ACC_CASE(4)  ACC_CASE(5)  ACC_CASE(6)  ACC_CASE(7)
                ACC_CASE(8)  ACC_CASE(9)  ACC_CASE(10) ACC_CASE(11)
                ACC_CASE(12) ACC_CASE(13) ACC_CASE(14) ACC_CASE(15)
            }
            ev = nev; ex = nex; b = nb;
        }
    }

    float i0  = 1.f/(sb0 +1e-16f), i1  = 1.f/(sb1 +1e-16f), i2  = 1.f/(sb2 +1e-16f), i3  = 1.f/(sb3 +1e-16f);
    float i4  = 1.f/(sb4 +1e-16f), i5  = 1.f/(sb5 +1e-16f), i6  = 1.f/(sb6 +1e-16f), i7  = 1.f/(sb7 +1e-16f);
    float i8  = 1.f/(sb8 +1e-16f), i9  = 1.f/(sb9 +1e-16f), i10 = 1.f/(sb10+1e-16f), i11 = 1.f/(sb11+1e-16f);
    float i12 = 1.f/(sb12+1e-16f), i13 = 1.f/(sb13+1e-16f), i14 = 1.f/(sb14+1e-16f), i15 = 1.f/(sb15+1e-16f);

    float4* op = (float4*)(out + (size_t)n * (HH * NB) + (size_t)lane * 4 * NB);
    op[0]  = make_float4(a0.x*i0,  a1.x*i1,  a2.x*i2,  a3.x*i3);
    op[1]  = make_float4(a4.x*i4,  a5.x*i5,  a6.x*i6,  a7.x*i7);
    op[2]  = make_float4(a8.x*i8,  a9.x*i9,  a10.x*i10, a11.x*i11);
    op[3]  = make_float4(a12.x*i12, a13.x*i13, a14.x*i14, a15.x*i15);
    op[4]  = make_float4(a0.y*i0,  a1.y*i1,  a2.y*i2,  a3.y*i3);
    op[5]  = make_float4(a4.y*i4,  a5.y*i5,  a6.y*i6,  a7.y*i7);
    op[6]  = make_float4(a8.y*i8,  a9.y*i9,  a10.y*i10, a11.y*i11);
    op[7]  = make_float4(a12.y*i12, a13.y*i13, a14.y*i14, a15.y*i15);
    op[8]  = make_float4(a0.z*i0,  a1.z*i1,  a2.z*i2,  a3.z*i3);
    op[9]  = make_float4(a4.z*i4,  a5.z*i5,  a6.z*i6,  a7.z*i7);
    op[10] = make_float4(a8.z*i8,  a9.z*i9,  a10.z*i10, a11.z*i11);
    op[11] = make_float4(a12.z*i12, a13.z*i13, a14.z*i14, a15.z*i15);
    op[12] = make_float4(a0.w*i0,  a1.w*i1,  a2.w*i2,  a3.w*i3);
    op[13] = make_float4(a4.w*i4,  a5.w*i5,  a6.w*i6,  a7.w*i7);
    op[14] = make_float4(a8.w*i8,  a9.w*i9,  a10.w*i10, a11.w*i11);
    op[15] = make_float4(a12.w*i12, a13.w*i13, a14.w*i14, a15.w*i15);
}

// ---------------- launcher ----------------
extern "C" void kernel_launch(void* const* d_in, const int* in_sizes, int n_in,
                              void* d_out, int out_size) {
    const float* x   = (const float*)d_in[0];
    const float* pos = (const float*)d_in[1];
    const int*   ei  = (const int*)d_in[2];
    const float* W1  = (const float*)d_in[3];
    const float* b1  = (const float*)d_in[4];
    const float* W2  = (const float*)d_in[5];
    const float* b2  = (const float*)d_in[6];
    const float* Wq  = (const float*)d_in[7];
    const float* bq  = (const float*)d_in[8];
    const float* Wk  = (const float*)d_in[9];
    // bk enters only via u = Wq·bk, constant per destination — cancels in grouped softmax
    float* out = (float*)d_out;

    float* pe;
    cudaGetSymbolAddress((void**)&pe, g_e);

    pack_x_kernel<<<(NN * 64 + 255) / 256, 256>>>(x);     // 0
    dim3 wgrid(64, 2);
    pack_w_kernel<<<wgrid, 256>>>(W1, W2);                // 1
    attn_prep_kernel<<<32, 256>>>(Wq, Wk, bq);            // 2
    prep_kernel<<<(EE + 255) / 256, 256>>>(ei, pos);      // 3
    scan_offsets_kernel<<<1, 1024>>>();                   // 4

    int gblocks = (NN + 127) / 128;
    gemm1_kernel<<<gblocks, 256>>>(b1, NN);               // 5 (ncu -s 5 target)
    scatter_edges_kernel<<<(EE + 255) / 256, 256>>>();    // 6
    gemm2_kernel<<<gblocks, 256>>>(b2, pe, NN);           // 7
    gemmP_kernel<<<gblocks, 256>>>(NN);                   // 8
    sv_kernel<<<(NN * 8 + 255) / 256, 256>>>();           // 9

    logit_kernel<<<(EE / 4 * 32 + 255) / 256, 256>>>();   // 10
    accum_kernel<<<(NN * 32 + 255) / 256, 256>>>(out);    // 11
}

// round 13
// speedup vs baseline: 1.2862x; 1.2862x over previous
#include <cuda_runtime.h>
#include <cuda_bf16.h>
#include <math.h>

#define NN 20000
#define EE 640000
#define HH 128
#define NB 16

// ---------------- scratch ----------------
__device__ int   g_src[EE];
__device__ int   g_dst[EE];
__device__ float g_e[(size_t)NN * 128];
__device__ float g_q[(size_t)NN * 128];
__device__ float g_k[(size_t)NN * 128];
__device__ float g_ev[(size_t)NN * 3];
__device__ int g_counts[NN];                 // 0 at prep entry; scan resets
__device__ int g_offs[NN + 1];
__device__ int g_cursor[NN];
__device__ unsigned g_pk[EE];                // src | (bin<<20), CSR-ordered by dst
__device__ unsigned short g_pdst[EE];        // dst per CSR position
__device__ float g_ex[EE];                   // exp(logit) per CSR position

// packed bf16 hi/lo pair tables (uint2 = {hi_pair, lo_pair}, pair = 2 adjacent cols)
__device__ uint2 g_xpk[(size_t)NN * 64];
__device__ uint2 g_tpk[(size_t)NN * 64];
__device__ uint2 g_epk[(size_t)NN * 64];
__device__ uint2 g_w1t[128 * 128];           // [col][j], j=0..127 (K=256)
__device__ uint2 g_w2t[128 * 64];
__device__ uint2 g_wqt[128 * 64];
__device__ uint2 g_wkt[128 * 64];

// ---------------- helpers ----------------
__device__ __forceinline__ void split2(float f0, float f1, unsigned& hi, unsigned& lo) {
    __nv_bfloat162 h = __floats2bfloat162_rn(f0, f1);
    float r0 = f0 - __bfloat162float(h.x);
    float r1 = f1 - __bfloat162float(h.y);
    __nv_bfloat162 l = __floats2bfloat162_rn(r0, r1);
    hi = *reinterpret_cast<unsigned*>(&h);
    lo = *reinterpret_cast<unsigned*>(&l);
}
__device__ __forceinline__ void mma16(float* c, unsigned a0, unsigned a1, unsigned a2, unsigned a3,
                                      unsigned b0, unsigned b1) {
    asm volatile(
        "mma.sync.aligned.m16n8k16.row.col.f32.bf16.bf16.f32 "
        "{%0,%1,%2,%3},{%4,%5,%6,%7},{%8,%9},{%0,%1,%2,%3};"
        : "+f"(c[0]), "+f"(c[1]), "+f"(c[2]), "+f"(c[3])
        : "r"(a0), "r"(a1), "r"(a2), "r"(a3), "r"(b0), "r"(b1));
}

// ---------------- prep: dtype-detect + normalize + histogram + ev (i<NN) ----------------
__global__ void prep_kernel(const int* __restrict__ ei_raw, const float* __restrict__ pos) {
    __shared__ int s_is64;
    if (threadIdx.x == 0) {
        int allzero = 1;
        #pragma unroll
        for (int i = 1; i < 128; i += 2)
            if (ei_raw[i] != 0) allzero = 0;
        s_is64 = allzero;
    }
    __syncthreads();
    int i = blockIdx.x * blockDim.x + threadIdx.x;
    if (i >= EE) return;
    int s, d;
    if (s_is64) {
        const long long* e = (const long long*)ei_raw;
        s = (int)e[i];
        d = (int)e[(size_t)EE + i];
    } else {
        s = ei_raw[i];
        d = ei_raw[EE + i];
    }
    g_src[i] = s;
    g_dst[i] = d;
    atomicAdd(&g_counts[d], 1);
    if (i < NN) {
        float vx = pos[d * 3 + 0] - pos[s * 3 + 0];
        float vy = pos[d * 3 + 1] - pos[s * 3 + 1];
        float vz = pos[d * 3 + 2] - pos[s * 3 + 2];
        float inv = 1.0f / (sqrtf(vx * vx + vy * vy + vz * vz) + 1e-8f);
        g_ev[i * 3 + 0] = vx * inv;
        g_ev[i * 3 + 1] = vy * inv;
        g_ev[i * 3 + 2] = vz * inv;
    }
}

// ---------------- scan (also resets counts) ----------------
__global__ void scan_offsets_kernel() {
    __shared__ int sh_carry;
    __shared__ int wsum[32];
    int tid = threadIdx.x, lane = tid & 31, wid = tid >> 5;
    if (tid == 0) sh_carry = 0;
    __syncthreads();
    for (int base = 0; base < NN; base += 1024) {
        int c0 = sh_carry;
        int i = base + tid;
        int v = (i < NN) ? g_counts[i] : 0;
        if (i < NN) g_counts[i] = 0;
        int x = v;
        #pragma unroll
        for (int off = 1; off < 32; off <<= 1) {
            int y = __shfl_up_sync(~0u, x, off);
            if (lane >= off) x += y;
        }
        if (lane == 31) wsum[wid] = x;
        __syncthreads();
        if (wid == 0) {
            int ws = wsum[lane];
            #pragma unroll
            for (int off = 1; off < 32; off <<= 1) {
                int y = __shfl_up_sync(~0u, ws, off);
                if (lane >= off) ws += y;
            }
            wsum[lane] = ws;
        }
        __syncthreads();
        int incl = c0 + x + (wid ? wsum[wid - 1] : 0);
        if (i < NN) { g_offs[i] = incl - v; g_cursor[i] = incl - v; }
        __syncthreads();
        if (tid == 1023) sh_carry = incl;
        __syncthreads();
    }
    if (threadIdx.x == 0) g_offs[NN] = sh_carry;
}

// ---------------- scatter: CSR order, pack src + angle bin, store dst ----------------
__global__ void scatter_edges_kernel() {
    int i = blockIdx.x * blockDim.x + threadIdx.x;
    if (i >= EE) return;
    int s = g_src[i];
    int d = g_dst[i];
    float c = g_ev[d * 3 + 0] * g_ev[s * 3 + 0]
            + g_ev[d * 3 + 1] * g_ev[s * 3 + 1]
            + g_ev[d * 3 + 2] * g_ev[s * 3 + 2];
    c = fminf(fmaxf(c, -1.f), 1.f);
    int cnt = 0;
    #pragma unroll
    for (int t = 0; t < 17; t++) cnt += ((-1.f + 0.125f * (float)t) < c) ? 1 : 0;
    int b = min(max(cnt - 1, 0), NB - 1);
    int p = atomicAdd(&g_cursor[d], 1);
    g_pk[p] = (unsigned)s | ((unsigned)b << 20);
    g_pdst[p] = (unsigned short)d;
}

// ---------------- packers ----------------
__global__ void pack_x_kernel(const float* __restrict__ x) {
    int idx = blockIdx.x * blockDim.x + threadIdx.x;
    if (idx >= NN * 64) return;
    float2 v = ((const float2*)x)[idx];
    unsigned h, l;
    split2(v.x, v.y, h, l);
    g_xpk[idx] = make_uint2(h, l);
}

__global__ void pack_w_kernel(const float* __restrict__ W1, const float* __restrict__ W2,
                              const float* __restrict__ Wq, const float* __restrict__ Wk) {
    int y = blockIdx.y;
    const float* W = (y == 0) ? W1 : (y == 1) ? W2 : (y == 2) ? Wq : Wk;
    uint2* Wt = (y == 0) ? g_w1t : (y == 1) ? g_w2t : (y == 2) ? g_wqt : g_wkt;
    int jmax = (y == 0) ? 128 : 64;
    int idx = blockIdx.x * blockDim.x + threadIdx.x;
    if (idx >= 128 * jmax) return;
    int col = idx / jmax, j = idx % jmax;
    float w0 = W[(size_t)(2 * j) * 128 + col];
    float w1 = W[(size_t)(2 * j + 1) * 128 + col];
    unsigned h, l;
    split2(w0, w1, h, l);
    Wt[col * jmax + j] = make_uint2(h, l);
}

// ================= packed bf16 GEMM =================
template<int K, int GATHER, int ACT, int WPK, int WF32>
__device__ __forceinline__ void gemm_pk_body(
    const uint2* __restrict__ Apk, const uint2* __restrict__ Wt,
    const float* __restrict__ bias, float* __restrict__ C,
    uint2* __restrict__ Cpk, int M)
{
    __shared__ __align__(16) uint2 Bs[2][128][20];
    int tid = threadIdx.x, lane = tid & 31, wid = tid >> 5;
    int gid = lane >> 2, tig = lane & 3;
    int warpRow = (wid & 3) * 32;
    int warpCol = (wid >> 2) * 64;
    int rowBase = blockIdx.x * 128;
    const int NT = K / 32;
    const int AJ = GATHER ? 64 : (K / 2);

    const uint2* ap[4];
    const uint2* ap2[4];
    #pragma unroll
    for (int i = 0; i < 4; i++) {
        int gr = rowBase + warpRow + i * 8 + gid;
        int row = (gr < M) ? gr : 0;
        if (GATHER) {
            ap[i]  = Apk + (size_t)g_src[row] * 64;
            ap2[i] = Apk + (size_t)g_dst[row] * 64;
        } else {
            ap[i] = Apk + (size_t)row * AJ;
        }
    }

    float acc[2][8][4];
    #pragma unroll
    for (int m = 0; m < 2; m++)
        #pragma unroll
        for (int n = 0; n < 8; n++)
            #pragma unroll
            for (int j = 0; j < 4; j++) acc[m][n][j] = 0.f;

    #pragma unroll
    for (int rr = 0; rr < 8; rr++) {
        int idx = tid + rr * 256;
        int col = idx >> 4, j = idx & 15;
        Bs[0][col][j] = Wt[(size_t)col * (K / 2) + j];
    }
    __syncthreads();

    #pragma unroll
    for (int t = 0; t < NT; t++) {
        if (t + 1 < NT) {
            #pragma unroll
            for (int rr = 0; rr < 8; rr++) {
                int idx = tid + rr * 256;
                int col = idx >> 4, j = idx & 15;
                Bs[(t + 1) & 1][col][j] = Wt[(size_t)col * (K / 2) + (t + 1) * 16 + j];
            }
        }
        const uint2* ab[4];
        int jt;
        if (GATHER) {
            bool first = t < NT / 2;
            #pragma unroll
            for (int i = 0; i < 4; i++) ab[i] = first ? ap[i] : ap2[i];
            jt = (first ? t : t - NT / 2) * 16;
        } else {
            #pragma unroll
            for (int i = 0; i < 4; i++) ab[i] = ap[i];
            jt = t * 16;
        }

        #pragma unroll
        for (int s = 0; s < 2; s++) {
            int ja = jt + s * 8;
            uint2 A0[4], A1[4];
            #pragma unroll
            for (int i = 0; i < 4; i++) {
                A0[i] = ab[i][ja + tig];
                A1[i] = ab[i][ja + tig + 4];
            }
            #pragma unroll
            for (int n = 0; n < 8; n++) {
                int col = warpCol + n * 8 + gid;
                uint2 b0 = Bs[t & 1][col][s * 8 + tig];
                uint2 b1 = Bs[t & 1][col][s * 8 + tig + 4];
                #pragma unroll
                for (int m = 0; m < 2; m++) {
                    mma16(acc[m][n], A0[2*m].x, A0[2*m+1].x, A1[2*m].x, A1[2*m+1].x, b0.x, b1.x);
                    mma16(acc[m][n], A0[2*m].x, A0[2*m+1].x, A1[2*m].x, A1[2*m+1].x, b0.y, b1.y);
                    mma16(acc[m][n], A0[2*m].y, A0[2*m+1].y, A1[2*m].y, A1[2*m+1].y, b0.x, b1.x);
                }
            }
        }
        __syncthreads();
    }

    #pragma unroll
    for (int m = 0; m < 2; m++) {
        int r0 = rowBase + warpRow + m * 16 + gid;
        int r1 = r0 + 8;
        #pragma unroll
        for (int n = 0; n < 8; n++) {
            int col = warpCol + n * 8 + tig * 2;
            float bz0 = bias[col], bz1 = bias[col + 1];
            float v0 = acc[m][n][0] + bz0, v1 = acc[m][n][1] + bz1;
            float v2 = acc[m][n][2] + bz0, v3 = acc[m][n][3] + bz1;
            if (ACT) {
                v0 = v0 / (1.f + expf(-v0)); v1 = v1 / (1.f + expf(-v1));
                v2 = v2 / (1.f + expf(-v2)); v3 = v3 / (1.f + expf(-v3));
            }
            int jout = (warpCol >> 1) + n * 4 + tig;
            if (r0 < M) {
                if (WF32) *(float2*)(C + (size_t)r0 * 128 + col) = make_float2(v0, v1);
                if (WPK) { unsigned h, l; split2(v0, v1, h, l); Cpk[(size_t)r0 * 64 + jout] = make_uint2(h, l); }
            }
            if (r1 < M) {
                if (WF32) *(float2*)(C + (size_t)r1 * 128 + col) = make_float2(v2, v3);
                if (WPK) { unsigned h, l; split2(v2, v3, h, l); Cpk[(size_t)r1 * 64 + jout] = make_uint2(h, l); }
            }
        }
    }
}

__global__ __launch_bounds__(256, 2) void gemm1_kernel(
    const float* __restrict__ b1, int M) {
    gemm_pk_body<256, 1, 1, 1, 0>(g_xpk, g_w1t, b1, nullptr, g_tpk, M);
}
__global__ __launch_bounds__(256, 2) void gemm2_kernel(
    const float* __restrict__ b2, float* __restrict__ e, int M) {
    gemm_pk_body<128, 0, 0, 1, 1>(g_tpk, g_w2t, b2, e, g_epk, M);
}
__global__ __launch_bounds__(256, 2) void gemm_qk_kernel(
    const float* __restrict__ bq, float* __restrict__ q,
    const float* __restrict__ bk, float* __restrict__ k, int M) {
    if (blockIdx.y == 0) gemm_pk_body<128, 0, 0, 0, 1>(g_epk, g_wqt, bq, q, nullptr, M);
    else                 gemm_pk_body<128, 0, 0, 0, 1>(g_epk, g_wkt, bk, k, nullptr, M);
}

// ---------------- pass 1: edge-parallel logits (quarter-warp per CSR position) ----------
__global__ __launch_bounds__(256) void logit_kernel() {
    int gw = (blockIdx.x * blockDim.x + threadIdx.x) >> 5;   // global warp
    int lane = threadIdx.x & 31;
    int sub = lane >> 3, sl = lane & 7;
    int pos = gw * 4 + sub;
    if (pos >= EE) return;

    unsigned pk = g_pk[pos];
    int s = pk & 0xFFFFF;
    int d = g_pdst[pos];

    const float4* kr = (const float4*)g_k + (size_t)s * 32;
    const float4* qr = (const float4*)g_q + (size_t)d * 32;

    float acc = 0.f;
    #pragma unroll
    for (int i = 0; i < 4; i++) {
        float4 a = qr[sl + 8 * i];
        float4 b = kr[sl + 8 * i];
        acc += a.x * b.x + a.y * b.y + a.z * b.z + a.w * b.w;
    }
    #pragma unroll
    for (int off = 4; off; off >>= 1) acc += __shfl_xor_sync(~0u, acc, off, 8);
    if (sl == 0) g_ex[pos] = expf(acc * 0.08838834764831843f);   // 1/sqrt(128)
}

// ---------------- pass 2: warp-per-node accumulate (no dot/exp) ----------------
#define ACC_CASE(B) case B: a##B.x += ex*ev.x; a##B.y += ex*ev.y; \
                            a##B.z += ex*ev.z; a##B.w += ex*ev.w; sb##B += ex; break;

__global__ __launch_bounds__(256, 2) void accum_kernel(float* __restrict__ out)
{
    int gw = (blockIdx.x * blockDim.x + threadIdx.x) >> 5;
    int lane = threadIdx.x & 31;
    if (gw >= NN) return;
    int n = gw;

    const float4* e4 = (const float4*)g_e;

    float4 z = make_float4(0.f, 0.f, 0.f, 0.f);
    float4 a0=z,a1=z,a2=z,a3=z,a4=z,a5=z,a6=z,a7=z,
           a8=z,a9=z,a10=z,a11=z,a12=z,a13=z,a14=z,a15=z;
    float sb0=0,sb1=0,sb2=0,sb3=0,sb4=0,sb5=0,sb6=0,sb7=0,
          sb8=0,sb9=0,sb10=0,sb11=0,sb12=0,sb13=0,sb14=0,sb15=0;

    int pos = g_offs[n];
    int end = g_offs[n + 1];

    if (pos < end) {
        unsigned pk = g_pk[pos];
        float ex = g_ex[pos];
        float4 ev = e4[(size_t)(pk & 0xFFFFF) * 32 + lane];
        int b = pk >> 20;

        for (; pos < end; pos++) {
            float4 nev = ev;
            float nex = ex;
            int nb = b;
            if (pos + 1 < end) {
                unsigned npk = g_pk[pos + 1];
                nex = g_ex[pos + 1];
                nev = e4[(size_t)(npk & 0xFFFFF) * 32 + lane];
                nb = npk >> 20;
            }
            switch (b) {
                ACC_CASE(0)  ACC_CASE(1)  ACC_CASE(2)  ACC_CASE(3)
                ACC_CASE(4)  ACC_CASE(5)  ACC_CASE(6)  ACC_CASE(7)
                ACC_CASE(8)  ACC_CASE(9)  ACC_CASE(10) ACC_CASE(11)
                ACC_CASE(12) ACC_CASE(13) ACC_CASE(14) ACC_CASE(15)
            }
            ev = nev; ex = nex; b = nb;
        }
    }

    float i0  = 1.f/(sb0 +1e-16f), i1  = 1.f/(sb1 +1e-16f), i2  = 1.f/(sb2 +1e-16f), i3  = 1.f/(sb3 +1e-16f);
    float i4  = 1.f/(sb4 +1e-16f), i5  = 1.f/(sb5 +1e-16f), i6  = 1.f/(sb6 +1e-16f), i7  = 1.f/(sb7 +1e-16f);
    float i8  = 1.f/(sb8 +1e-16f), i9  = 1.f/(sb9 +1e-16f), i10 = 1.f/(sb10+1e-16f), i11 = 1.f/(sb11+1e-16f);
    float i12 = 1.f/(sb12+1e-16f), i13 = 1.f/(sb13+1e-16f), i14 = 1.f/(sb14+1e-16f), i15 = 1.f/(sb15+1e-16f);

    float4* op = (float4*)(out + (size_t)n * (HH * NB) + (size_t)lane * 4 * NB);
    op[0]  = make_float4(a0.x*i0,  a1.x*i1,  a2.x*i2,  a3.x*i3);
    op[1]  = make_float4(a4.x*i4,  a5.x*i5,  a6.x*i6,  a7.x*i7);
    op[2]  = make_float4(a8.x*i8,  a9.x*i9,  a10.x*i10, a11.x*i11);
    op[3]  = make_float4(a12.x*i12, a13.x*i13, a14.x*i14, a15.x*i15);
    op[4]  = make_float4(a0.y*i0,  a1.y*i1,  a2.y*i2,  a3.y*i3);
    op[5]  = make_float4(a4.y*i4,  a5.y*i5,  a6.y*i6,  a7.y*i7);
    op[6]  = make_float4(a8.y*i8,  a9.y*i9,  a10.y*i10, a11.y*i11);
    op[7]  = make_float4(a12.y*i12, a13.y*i13, a14.y*i14, a15.y*i15);
    op[8]  = make_float4(a0.z*i0,  a1.z*i1,  a2.z*i2,  a3.z*i3);
    op[9]  = make_float4(a4.z*i4,  a5.z*i5,  a6.z*i6,  a7.z*i7);
    op[10] = make_float4(a8.z*i8,  a9.z*i9,  a10.z*i10, a11.z*i11);
    op[11] = make_float4(a12.z*i12, a13.z*i13, a14.z*i14, a15.z*i15);
    op[12] = make_float4(a0.w*i0,  a1.w*i1,  a2.w*i2,  a3.w*i3);
    op[13] = make_float4(a4.w*i4,  a5.w*i5,  a6.w*i6,  a7.w*i7);
    op[14] = make_float4(a8.w*i8,  a9.w*i9,  a10.w*i10, a11.w*i11);
    op[15] = make_float4(a12.w*i12, a13.w*i13, a14.w*i14, a15.w*i15);
}

// ---------------- launcher: fork-join overlap of CSR chain vs pack+GEMM chain ----------
extern "C" void kernel_launch(void* const* d_in, const int* in_sizes, int n_in,
                              void* d_out, int out_size) {
    const float* x   = (const float*)d_in[0];
    const float* pos = (const float*)d_in[1];
    const int*   ei  = (const int*)d_in[2];
    const float* W1  = (const float*)d_in[3];
    const float* b1  = (const float*)d_in[4];
    const float* W2  = (const float*)d_in[5];
    const float* b2  = (const float*)d_in[6];
    const float* Wq  = (const float*)d_in[7];
    const float* bq  = (const float*)d_in[8];
    const float* Wk  = (const float*)d_in[9];
    const float* bk  = (const float*)d_in[10];
    float* out = (float*)d_out;

    float *pe, *pq, *pk;
    cudaGetSymbolAddress((void**)&pe, g_e);
    cudaGetSymbolAddress((void**)&pq, g_q);
    cudaGetSymbolAddress((void**)&pk, g_k);

    cudaStream_t s2;
    cudaStreamCreateWithFlags(&s2, cudaStreamNonBlocking);
    cudaEvent_t evFork, evPack, evPrep, evScat;
    cudaEventCreateWithFlags(&evFork, cudaEventDisableTiming);
    cudaEventCreateWithFlags(&evPack, cudaEventDisableTiming);
    cudaEventCreateWithFlags(&evPrep, cudaEventDisableTiming);
    cudaEventCreateWithFlags(&evScat, cudaEventDisableTiming);

    // fork side stream off the main (capture) stream
    cudaEventRecord(evFork, 0);
    cudaStreamWaitEvent(s2, evFork, 0);

    // side stream: packs (independent of indices)
    pack_x_kernel<<<(NN * 64 + 255) / 256, 256, 0, s2>>>(x);
    dim3 wgrid(64, 4);
    pack_w_kernel<<<wgrid, 256, 0, s2>>>(W1, W2, Wq, Wk);
    cudaEventRecord(evPack, s2);

    // main stream: prep (indices + ev)
    prep_kernel<<<(EE + 255) / 256, 256>>>(ei, pos);
    cudaEventRecord(evPrep, 0);

    // side stream: CSR chain after prep
    cudaStreamWaitEvent(s2, evPrep, 0);
    scan_offsets_kernel<<<1, 1024, 0, s2>>>();
    scatter_edges_kernel<<<(EE + 255) / 256, 256, 0, s2>>>();
    cudaEventRecord(evScat, s2);

    // main stream: GEMM chain (needs packs + prep's src/dst)
    cudaStreamWaitEvent(0, evPack, 0);
    int gblocks = (NN + 127) / 128;
    gemm1_kernel<<<gblocks, 256>>>(b1, NN);
    gemm2_kernel<<<gblocks, 256>>>(b2, pe, NN);
    dim3 qkgrid(gblocks, 2);
    gemm_qk_kernel<<<qkgrid, 256>>>(bq, pq, bk, pk, NN);

    // join: logit/accum need scatter's CSR + q/k
    cudaStreamWaitEvent(0, evScat, 0);
    logit_kernel<<<(EE / 4 * 32 + 255) / 256, 256>>>();
    accum_kernel<<<(NN * 32 + 255) / 256, 256>>>(out);
}